// round 12
// baseline (speedup 1.0000x reference)
#include <cuda_runtime.h>
#include <cstdint>

// Scratch: 8 channel-groups, each acc_g[k*8 + cc] packed
// (sortable_value:32 | (N-j):32). Group = N*8*8B = 32MB (L2-resident).
__device__ unsigned long long g_acc[32000000];

__device__ __forceinline__ unsigned f2sort(float f) {
    unsigned u = __float_as_uint(f);
    return (u & 0x80000000u) ? ~u : (u | 0x80000000u);
}
__device__ __forceinline__ float sort2f(unsigned s) {
    unsigned u = (s & 0x80000000u) ? (s ^ 0x80000000u) : ~s;
    return __uint_as_float(u);
}

// -------------------- Pass 1: scatter, one channel-group (8 ch) --------------------
// Each thread: 4 consecutive points x 8 channels; LDG.128 src loads, then
// 8 contiguous REDG.64 per point (64B cluster).
__global__ void scatter8_kernel(const float* __restrict__ src,
                                const int* __restrict__ index,
                                int N, int c0,
                                unsigned long long* __restrict__ acc) {
    int t  = threadIdx.x;
    int j0 = blockIdx.x * 1024 + t * 4;
    if (j0 >= N) return;

    if (j0 + 4 <= N) {
        int4 idx4 = __ldcs(reinterpret_cast<const int4*>(index + j0));
        float4 v[8];
#pragma unroll
        for (int c = 0; c < 8; ++c)
            v[c] = __ldcs(reinterpret_cast<const float4*>(
                src + (size_t)(c0 + c) * N + j0));

        int kk[4] = {idx4.x, idx4.y, idx4.z, idx4.w};
#pragma unroll
        for (int i = 0; i < 4; ++i) {
            unsigned long long lowkey = (unsigned)(N - (j0 + i));
            unsigned long long* ap = acc + (size_t)kk[i] * 8;
#pragma unroll
            for (int c = 0; c < 8; ++c) {
                float fv = (i == 0) ? v[c].x : (i == 1) ? v[c].y
                                             : (i == 2) ? v[c].z : v[c].w;
                unsigned long long p =
                    ((unsigned long long)f2sort(fv) << 32) | lowkey;
                atomicMax(ap + c, p);
            }
        }
    } else {
        for (int i = 0; i < 4 && j0 + i < N; ++i) {
            int j = j0 + i;
            int k = __ldcs(index + j);
            unsigned long long lowkey = (unsigned)(N - j);
            unsigned long long* ap = acc + (size_t)k * 8;
#pragma unroll
            for (int c = 0; c < 8; ++c) {
                float fv = __ldcs(src + (size_t)(c0 + c) * N + j);
                unsigned long long p =
                    ((unsigned long long)f2sort(fv) << 32) | lowkey;
                atomicMax(ap + c, p);
            }
        }
    }
}

// -------------------- Pass 2: per-group finalize (8 channels) --------------------
// Block (256 thr) handles a 128k x 8c tile. Phase A: ll2 coalesced acc reads
// -> smem[cc][kk]. Phase B: float4 src reads + float4 out/arg writes.
__global__ void finalize8_kernel(const float* __restrict__ src,
                                 float* __restrict__ out,
                                 float* __restrict__ arg,
                                 int N, int writeArg, int c0,
                                 const unsigned long long* __restrict__ acc) {
    __shared__ __align__(16) float s_val[8][132];
    __shared__ __align__(16) float s_arg[8][132];
    int k0  = blockIdx.x * 128;
    int tid = threadIdx.x;

    if (k0 + 128 <= N) {
        const longlong2* accv =
            reinterpret_cast<const longlong2*>(acc + (size_t)k0 * 8);
#pragma unroll
        for (int i = 0; i < 2; ++i) {
            int idx2 = i * 256 + tid;          // 0..511 ll2 in tile
            longlong2 p2 = __ldcs(accv + idx2);
            int e  = idx2 * 2;                  // element index kk*8+cc
            int kk = e >> 3;
            int cc = e & 7;
            {
                unsigned long long p = (unsigned long long)p2.x;
                unsigned low = (unsigned)p, hi = (unsigned)(p >> 32);
                s_val[cc][kk] = low ? sort2f(hi) : __int_as_float(0xff800000);
                s_arg[cc][kk] = (float)(low ? (N - (int)low) : N);
            }
            {
                unsigned long long p = (unsigned long long)p2.y;
                unsigned low = (unsigned)p, hi = (unsigned)(p >> 32);
                s_val[cc + 1][kk] = low ? sort2f(hi) : __int_as_float(0xff800000);
                s_arg[cc + 1][kk] = (float)(low ? (N - (int)low) : N);
            }
        }
        __syncthreads();

        float fN = (float)N;
        int c  = tid >> 5;            // 0..7
        int kk = (tid & 31) * 4;      // 0..124
        size_t gidx = (size_t)(c0 + c) * N + (k0 + kk);
        float4 sv = __ldcs(reinterpret_cast<const float4*>(src + gidx));
        float4 sg = *reinterpret_cast<const float4*>(&s_val[c][kk]);
        float4 sa = *reinterpret_cast<const float4*>(&s_arg[c][kk]);
        float4 ov, av;
        ov.x = fmaxf(sv.x, sg.x); av.x = (sg.x >= sv.x) ? sa.x : fN;
        ov.y = fmaxf(sv.y, sg.y); av.y = (sg.y >= sv.y) ? sa.y : fN;
        ov.z = fmaxf(sv.z, sg.z); av.z = (sg.z >= sv.z) ? sa.z : fN;
        ov.w = fmaxf(sv.w, sg.w); av.w = (sg.w >= sv.w) ? sa.w : fN;
        __stcs(reinterpret_cast<float4*>(out + gidx), ov);
        if (writeArg) __stcs(reinterpret_cast<float4*>(arg + gidx), av);
    } else {
        for (int e = tid; e < 128 * 8; e += blockDim.x) {
            int kk = e >> 3;
            int cc = e & 7;
            int k  = k0 + kk;
            float val = __int_as_float(0xff800000);
            int a = N;
            if (k < N) {
                unsigned long long p = acc[(size_t)k * 8 + cc];
                unsigned low = (unsigned)p, hi = (unsigned)(p >> 32);
                if (low) { val = sort2f(hi); a = N - (int)low; }
            }
            s_val[cc][kk] = val;
            s_arg[cc][kk] = (float)a;
        }
        __syncthreads();
        for (int e = tid; e < 8 * 128; e += blockDim.x) {
            int c  = e >> 7;
            int kk = e & 127;
            int k  = k0 + kk;
            if (k < N) {
                size_t idx = (size_t)(c0 + c) * N + k;
                float sv  = src[idx];
                float seg = s_val[c][kk];
                out[idx] = fmaxf(sv, seg);
                if (writeArg) arg[idx] = (seg >= sv) ? s_arg[c][kk] : (float)N;
            }
        }
    }
}

// -------------------- Generic fallback (C != 64) --------------------
__global__ void scatter_gen_kernel(const float* __restrict__ src,
                                   const int* __restrict__ index,
                                   int C, int N) {
    int j = blockIdx.x * blockDim.x + threadIdx.x;
    if (j >= N) return;
    int k = index[j];
    unsigned long long* accp = g_acc + (size_t)k * C;
    unsigned lowkey = (unsigned)(N - j);
    for (int c = 0; c < C; ++c) {
        float v = __ldg(src + (size_t)c * N + j);
        unsigned long long p =
            ((unsigned long long)f2sort(v) << 32) | (unsigned long long)lowkey;
        atomicMax(accp + c, p);
    }
}

__global__ void finalize_gen_kernel(const float* __restrict__ src,
                                    float* __restrict__ out,
                                    float* __restrict__ arg,
                                    int C, int N, int writeArg) {
    long long t = (long long)blockIdx.x * blockDim.x + threadIdx.x;
    long long total = (long long)C * N;
    if (t >= total) return;
    int c = (int)(t / N);
    int k = (int)(t % N);
    unsigned long long p = g_acc[(size_t)k * C + c];
    unsigned low = (unsigned)p, hi = (unsigned)(p >> 32);
    float seg = low ? sort2f(hi) : __int_as_float(0xff800000);
    int   a   = low ? (N - (int)low) : N;
    float sv = src[t];
    out[t] = fmaxf(sv, seg);
    if (writeArg) arg[t] = (float)((seg >= sv) ? a : N);
}

extern "C" void kernel_launch(void* const* d_in, const int* in_sizes, int n_in,
                              void* d_out, int out_size) {
    const float* src   = (const float*)d_in[0];
    const int*   index = (const int*)d_in[1];   // JAX x64-disabled: int32

    int N = in_sizes[1];
    int C = (N > 0) ? (in_sizes[0] / N) : 0;
    if (N <= 0 || C <= 0) return;

    size_t cn = (size_t)C * (size_t)N;

    unsigned char* accp = nullptr;
    cudaGetSymbolAddress((void**)&accp, g_acc);

    float* out = (float*)d_out;
    int writeArg = ((size_t)out_size >= 2 * cn) ? 1 : 0;
    float* arg = out + cn;

    if (C == 64) {
        static bool s_init = false;
        static cudaStream_t s1, s2;
        static cudaEvent_t evRoot, evM[8], evPre[8], evS[8], evJ;
        if (!s_init) {
            cudaStreamCreateWithFlags(&s1, cudaStreamNonBlocking);
            cudaStreamCreateWithFlags(&s2, cudaStreamNonBlocking);
            cudaEventCreateWithFlags(&evRoot, cudaEventDisableTiming);
            for (int i = 0; i < 8; ++i) {
                cudaEventCreateWithFlags(&evM[i], cudaEventDisableTiming);
                cudaEventCreateWithFlags(&evPre[i], cudaEventDisableTiming);
                cudaEventCreateWithFlags(&evS[i], cudaEventDisableTiming);
            }
            cudaEventCreateWithFlags(&evJ, cudaEventDisableTiming);
            s_init = true;
        }

        size_t grpBytes = (size_t)N * 8 * sizeof(unsigned long long); // 32MB
        int sBlocks = (N + 1023) / 1024;
        int fBlocks = (N + 127) / 128;

        // Capture fork: s2 waits an origin-stream event before its first op.
        cudaEventRecord(evRoot, 0);
        cudaStreamWaitEvent(s2, evRoot, 0);

        // Pipeline with TRUE overlap: evPre[g] (recorded on stream 0 right
        // before scatter(g) launches, i.e. fires when ms(g) completes) gates
        // ms(g+1) on s2 -> one memset overlaps one scatter.
        //   s2:  ms(0) | ms(1)∥sc(0) | ms(2)∥sc(1) | ...
        //   0 :        sc(0)  sc(1)  sc(2) ...
        //   s1:              fin(0)  fin(1) ...
        for (int g = 0; g < 8; ++g) {
            unsigned long long* acc_g =
                reinterpret_cast<unsigned long long*>(accp + (size_t)g * grpBytes);

            if (g == 0) {
                cudaMemsetAsync(accp, 0, grpBytes, s2);
                cudaEventRecord(evM[0], s2);
            }
            cudaStreamWaitEvent(0, evM[g], 0);
            cudaEventRecord(evPre[g], 0);           // fires as sc(g) starts
            if (g + 1 < 8) {
                cudaStreamWaitEvent(s2, evPre[g], 0);
                cudaMemsetAsync(accp + (size_t)(g + 1) * grpBytes, 0, grpBytes, s2);
                cudaEventRecord(evM[g + 1], s2);
            }
            scatter8_kernel<<<sBlocks, 256, 0, 0>>>(src, index, N, g * 8, acc_g);
            cudaEventRecord(evS[g], 0);

            cudaStreamWaitEvent(s1, evS[g], 0);
            finalize8_kernel<<<fBlocks, 256, 0, s1>>>(
                src, out, arg, N, writeArg, g * 8, acc_g);
        }
        cudaEventRecord(evJ, s1);
        cudaStreamWaitEvent(0, evJ, 0);
    } else {
        cudaMemsetAsync(accp, 0, cn * sizeof(unsigned long long), 0);
        int threads = 256;
        scatter_gen_kernel<<<(N + threads - 1) / threads, threads>>>(src, index, C, N);
        long long total = (long long)C * N;
        finalize_gen_kernel<<<(int)((total + threads - 1) / threads), threads>>>(
            src, out, arg, C, N, writeArg);
    }
}